// round 6
// baseline (speedup 1.0000x reference)
#include <cuda_runtime.h>
#include <cuda_bf16.h>
#include <math.h>

#define BATCHN 256
#define SEQN   512
#define IN_DIM 64
#define HID    256
#define NCTA   148
#define NTHR   256
#define LDX    (SEQN * IN_DIM)

// ---------------- persistent device state (no allocation allowed) -----------
__device__ float g_x[(size_t)BATCHN * SEQN * IN_DIM];   // sanitized input
__device__ float g_h0buf[2][BATCHN * HID];
__device__ float g_h1[BATCHN * HID];
__device__ float g_z0[BATCHN * HID];
__device__ float g_rh0[BATCHN * HID];
__device__ float g_z1[BATCHN * HID];
__device__ float g_rh1[BATCHN * HID];

__device__ unsigned g_count = 0;          // always returns to 0
__device__ volatile unsigned g_gen = 0;   // monotonic generation counter

// ---------------------------- grid barrier ----------------------------------
__device__ __forceinline__ void grid_sync() {
    __syncthreads();
    if (threadIdx.x == 0) {
        __threadfence();                    // release our global writes
        unsigned gen = g_gen;               // read BEFORE arriving
        unsigned a = atomicAdd(&g_count, 1u);
        if (a == NCTA - 1) {
            g_count = 0;
            __threadfence();
            g_gen = gen + 1;                // release everyone
        } else {
            while (g_gen == gen) { }        // tight L2 spin
            __threadfence();                // acquire
        }
    }
    __syncthreads();
}

// ---------------------------- shared memory ---------------------------------
struct __align__(16) SmemT {
    float ws[2][32][32];   // W tiles (k-major, 32 n)      8 KB
    float as[2][32][36];   // A tiles (m-major, padded)    9 KB
    float red[16];
};

__device__ __forceinline__ void cp16(void* dst_smem, const void* src_gmem) {
    unsigned u = (unsigned)__cvta_generic_to_shared(dst_smem);
    asm volatile("cp.async.cg.shared.global [%0], [%1], 16;"
                 :: "r"(u), "l"(src_gmem) : "memory");
}

// One 32x32 tile of C = [A0 | A1] @ W (+bias), fused GRU epilogue.
// 256 threads: 16x16 thread grid, 2x2 microtile per thread.
//   gate : sg = sigmoid(v); n<HID -> zb, n>=HID -> rb = sg * hg
//   cand : hw = (1-z)*hold + z*tanh(v)
__device__ void gemm_tile(
    SmemT* s, int tM, int tN,
    const float* A0, int ldA0, const float* A1, int ldA1, int K0, int K,
    const float* W, int ldW, const float* bias,
    bool gate, const float* zb_r, float* zb_w, float* rb, const float* hg,
    const float* hold, float* hw)
{
    const int tid = threadIdx.x;
    const int tm = tid >> 4;          // 0..15 -> rows tm*2, tm*2+1
    const int tn = tid & 15;          // 0..15 -> cols tn*2, tn*2+1

    // loader lane mapping
    const int wk = tid >> 3;          // 0..31 W row
    const int wn = (tid & 7) * 4;     // W col group (float4)
    const int am = tid >> 3;          // 0..31 A row
    const int ak = (tid & 7) * 4;     // A k group (float4)

    float acc[2][2] = {{0.f, 0.f}, {0.f, 0.f}};

    const float* A0b = A0 + (size_t)tM * 32 * ldA0;
    const float* A1b = A1 + (size_t)tM * 32 * ldA1;
    const float* Wb  = W + tN * 32;

    const int nst = K >> 5;

    auto load = [&](int buf, int k0) {
        const float* Ab; int ldA; int kb;
        if (k0 < K0) { Ab = A0b; ldA = ldA0; kb = k0; }
        else         { Ab = A1b; ldA = ldA1; kb = k0 - K0; }
        cp16(&s->ws[buf][wk][wn], Wb + (size_t)(k0 + wk) * ldW + wn);
        cp16(&s->as[buf][am][ak], Ab + (size_t)am * ldA + kb + ak);
        asm volatile("cp.async.commit_group;" ::: "memory");
    };

    load(0, 0);
    for (int stg = 0; stg < nst; ++stg) {
        int buf = stg & 1;
        if (stg + 1 < nst) {
            load(buf ^ 1, (stg + 1) << 5);
            asm volatile("cp.async.wait_group 1;" ::: "memory");
        } else {
            asm volatile("cp.async.wait_group 0;" ::: "memory");
        }
        __syncthreads();
#pragma unroll
        for (int w0 = 0; w0 < 32; w0 += 8) {
            float a0[8], a1[8];
            *(float4*)&a0[0] = *(const float4*)&s->as[buf][tm * 2][w0];
            *(float4*)&a0[4] = *(const float4*)&s->as[buf][tm * 2][w0 + 4];
            *(float4*)&a1[0] = *(const float4*)&s->as[buf][tm * 2 + 1][w0];
            *(float4*)&a1[4] = *(const float4*)&s->as[buf][tm * 2 + 1][w0 + 4];
#pragma unroll
            for (int kk = 0; kk < 8; kk++) {
                float2 wv = *(const float2*)&s->ws[buf][w0 + kk][tn * 2];
                acc[0][0] += a0[kk] * wv.x;
                acc[0][1] += a0[kk] * wv.y;
                acc[1][0] += a1[kk] * wv.x;
                acc[1][1] += a1[kk] * wv.y;
            }
        }
        __syncthreads();
    }

    const int b0 = tM * 32 + tm * 2;
    const int n0 = tN * 32 + tn * 2;
#pragma unroll
    for (int i = 0; i < 2; i++) {
        int b = b0 + i;
#pragma unroll
        for (int j = 0; j < 2; j++) {
            int n = n0 + j;
            float v = acc[i][j] + bias[n];
            if (gate) {
                float sg = 1.f / (1.f + __expf(-v));
                if (n < HID) zb_w[b * HID + n] = sg;
                else {
                    int c = n - HID;
                    rb[b * HID + c] = sg * hg[b * HID + c];
                }
            } else {
                float z = zb_r[b * HID + n];
                hw[b * HID + n] = (1.f - z) * hold[b * HID + n] + z * tanhf(v);
            }
        }
    }
}

// ---------------------------- persistent kernel -----------------------------
__global__ void __launch_bounds__(NTHR, 1)
rnn_kernel(const float* __restrict__ x,
           const float* __restrict__ Wz0, const float* __restrict__ bz0,
           const float* __restrict__ Wc0, const float* __restrict__ bc0,
           const float* __restrict__ Wz1, const float* __restrict__ bz1,
           const float* __restrict__ Wc1, const float* __restrict__ bc1,
           const float* __restrict__ gamma, const float* __restrict__ beta,
           float* __restrict__ out)
{
    __shared__ SmemT s;
    const int bid = blockIdx.x;

    // ---- init: sanitize x (NaN->0, Inf->sign*10), zero states ----
    {
        int gtid = bid * NTHR + threadIdx.x;
        int gs = NCTA * NTHR;
        for (size_t i = gtid; i < (size_t)BATCHN * SEQN * IN_DIM; i += gs) {
            float v = x[i];
            if (v != v) v = 0.f;
            else if (isinf(v)) v = (v > 0.f) ? 10.f : -10.f;
            g_x[i] = v;
        }
        for (int i = gtid; i < BATCHN * HID; i += gs) {
            g_h0buf[0][i] = 0.f;
            g_h1[i] = 0.f;
        }
    }
    grid_sync();

    // superstep st: phase A = gates0(st) || gates1(st-1)
    //               phase B = cand0(st)  || cand1(st-1)
    for (int st = 0; st <= SEQN; ++st) {
        float* h0cur = g_h0buf[st & 1];
        float* h0nxt = g_h0buf[(st + 1) & 1];
        const float* xt = g_x + (size_t)st * IN_DIM;   // row stride LDX

        // ---------------- phase A (static mixed schedule) ----------------
        {
            const bool doG1 = (st > 0);
            const bool doG0 = (st < SEQN);
            int g1 = -1, g0a = -1, g0b = -1;
            if (bid < 108)      { g1 = bid; g0a = bid; }
            else if (bid < 128) { g1 = bid; }
            else if (bid < 138) { g0a = 108 + 2 * (bid - 128); g0b = g0a + 1; }

            if (doG1 && g1 >= 0)
                gemm_tile(&s, g1 >> 4, g1 & 15,
                          g_h1, HID, h0cur, HID, HID, 2 * HID,
                          Wz1, 3 * HID, bz1,
                          true, nullptr, g_z1, g_rh1, g_h1, nullptr, nullptr);
            if (doG0 && g0a >= 0)
                gemm_tile(&s, g0a >> 4, g0a & 15,
                          h0cur, HID, xt, LDX, HID, HID + IN_DIM,
                          Wz0, 3 * HID, bz0,
                          true, nullptr, g_z0, g_rh0, h0cur, nullptr, nullptr);
            if (doG0 && g0b >= 0)
                gemm_tile(&s, g0b >> 4, g0b & 15,
                          h0cur, HID, xt, LDX, HID, HID + IN_DIM,
                          Wz0, 3 * HID, bz0,
                          true, nullptr, g_z0, g_rh0, h0cur, nullptr, nullptr);
        }
        grid_sync();

        // ---------------- phase B ----------------
        {
            if (st > 0 && bid < 64) {
                gemm_tile(&s, bid >> 3, bid & 7,
                          g_rh1, HID, h0cur, HID, HID, 2 * HID,
                          Wc1, HID, bc1,
                          false, g_z1, nullptr, nullptr, nullptr, g_h1, g_h1);
            } else if (st < SEQN && bid >= 64 && bid < 128) {
                int t = bid - 64;
                gemm_tile(&s, t >> 3, t & 7,
                          g_rh0, HID, xt, LDX, HID, HID + IN_DIM,
                          Wc0, HID, bc0,
                          false, g_z0, nullptr, nullptr, nullptr, h0cur, h0nxt);
            }
        }
        grid_sync();
    }

    // ---------------- LayerNorm on final h1 ----------------
    {
        const int tid = threadIdx.x;
        const int wid = tid >> 5, lane = tid & 31;
        for (int b = bid; b < BATCHN; b += NCTA) {
            float v = g_h1[b * HID + tid];
            float sum = v, sq = v * v;
#pragma unroll
            for (int off = 16; off; off >>= 1) {
                sum += __shfl_xor_sync(0xFFFFFFFFu, sum, off);
                sq  += __shfl_xor_sync(0xFFFFFFFFu, sq,  off);
            }
            if (lane == 0) { s.red[wid] = sum; s.red[8 + wid] = sq; }
            __syncthreads();
            float ts = 0.f, tq = 0.f;
#pragma unroll
            for (int w = 0; w < 8; w++) { ts += s.red[w]; tq += s.red[8 + w]; }
            float mean = ts * (1.f / HID);
            float var  = tq * (1.f / HID) - mean * mean;
            float rstd = rsqrtf(var + 1e-5f);
            out[b * HID + tid] = (v - mean) * rstd * gamma[tid] + beta[tid];
            __syncthreads();
        }
    }
}

extern "C" void kernel_launch(void* const* d_in, const int* in_sizes, int n_in,
                              void* d_out, int out_size) {
    (void)in_sizes; (void)n_in; (void)out_size;
    const float* x     = (const float*)d_in[0];
    const float* Wz0   = (const float*)d_in[1];
    const float* bz0   = (const float*)d_in[2];
    const float* Wc0   = (const float*)d_in[3];
    const float* bc0   = (const float*)d_in[4];
    const float* Wz1   = (const float*)d_in[5];
    const float* bz1   = (const float*)d_in[6];
    const float* Wc1   = (const float*)d_in[7];
    const float* bc1   = (const float*)d_in[8];
    const float* gamma = (const float*)d_in[9];
    const float* beta  = (const float*)d_in[10];
    float* out = (float*)d_out;

    rnn_kernel<<<NCTA, NTHR>>>(x, Wz0, bz0, Wc0, bc0,
                               Wz1, bz1, Wc1, bc1, gamma, beta, out);
}

// round 7
// speedup vs baseline: 1.0930x; 1.0930x over previous
#include <cuda_runtime.h>
#include <cuda_bf16.h>
#include <math.h>

#define BATCHN 256
#define SEQN   512
#define IN_DIM 64
#define HID    256
#define NCTA   148
#define NTHR   256
#define LDXE   (SEQN * IN_DIM)

typedef __nv_bfloat16  bf16;
typedef __nv_bfloat162 bf162;

// ---------------- persistent device state (no allocation allowed) -----------
__device__ bf16  g_xhi[(size_t)BATCHN * SEQN * IN_DIM];
__device__ bf16  g_xlo[(size_t)BATCHN * SEQN * IN_DIM];
__device__ float g_h0f[2][BATCHN * HID];
__device__ bf16  g_h0hi[2][BATCHN * HID];
__device__ bf16  g_h0lo[2][BATCHN * HID];
__device__ float g_h1f[BATCHN * HID];
__device__ bf16  g_h1hi[BATCHN * HID];
__device__ bf16  g_h1lo[BATCHN * HID];
__device__ float g_z0[BATCHN * HID];
__device__ float g_z1[BATCHN * HID];
__device__ bf16  g_rh0hi[BATCHN * HID];
__device__ bf16  g_rh0lo[BATCHN * HID];
__device__ bf16  g_rh1hi[BATCHN * HID];
__device__ bf16  g_rh1lo[BATCHN * HID];

__device__ unsigned g_count = 0;
__device__ volatile unsigned g_gen = 0;

// ---------------------------- grid barrier ----------------------------------
__device__ __forceinline__ void grid_sync() {
    __syncthreads();
    if (threadIdx.x == 0) {
        __threadfence();
        unsigned gen = g_gen;
        unsigned a = atomicAdd(&g_count, 1u);
        if (a == NCTA - 1) {
            g_count = 0;
            __threadfence();
            g_gen = gen + 1;
        } else {
            while (g_gen == gen) { }
            __threadfence();
        }
    }
    __syncthreads();
}

// --------------------- shared memory layout (dynamic) -----------------------
// sAhi: 32*520 elems | sAlo: 32*520 | sBhi: 16*520 | sBlo: 16*520
#define SA_ELEMS (32 * 520)
#define SB_ELEMS (16 * 520)
#define SMEM_ELEMS (2 * SA_ELEMS + 2 * SB_ELEMS)
#define SMEM_BYTES (SMEM_ELEMS * 2)

// ------------------------------- mma helper ---------------------------------
__device__ __forceinline__ void mma16816(float* c,
    unsigned a0, unsigned a1, unsigned a2, unsigned a3,
    unsigned b0, unsigned b1)
{
    asm("mma.sync.aligned.m16n8k16.row.col.f32.bf16.bf16.f32 "
        "{%0,%1,%2,%3}, {%4,%5,%6,%7}, {%8,%9}, {%0,%1,%2,%3};"
        : "+f"(c[0]), "+f"(c[1]), "+f"(c[2]), "+f"(c[3])
        : "r"(a0), "r"(a1), "r"(a2), "r"(a3), "r"(b0), "r"(b1));
}

// One K-section of the 3-term split MMA loop.
//  Ahi/Alo: global, pre-offset to this warp's m0 row, k=0 of section.
//  sBhi/sBlo: smem W^T, pre-offset to this warp's nloc row; kbase = section k offset.
template<int KSEC, int NF>
__device__ __forceinline__ void mma_sec(
    const bf16* __restrict__ Ahi, const bf16* __restrict__ Alo, int ldA,
    const bf16* sBhi, const bf16* sBlo, int ldWt, int kbase,
    float (&acc)[NF][4])
{
    const int lane = threadIdx.x & 31;
    const int g = lane >> 2, q = lane & 3;
    const bf16* ah = Ahi + (size_t)g * ldA + q * 2;
    const bf16* al = Alo + (size_t)g * ldA + q * 2;
    const size_t rstep = (size_t)8 * ldA;
    const bf16* bh[NF];
    const bf16* bl[NF];
#pragma unroll
    for (int f = 0; f < NF; f++) {
        bh[f] = sBhi + (size_t)(f * 8 + g) * ldWt + kbase + q * 2;
        bl[f] = sBlo + (size_t)(f * 8 + g) * ldWt + kbase + q * 2;
    }
#pragma unroll
    for (int k = 0; k < KSEC; k += 16) {
        unsigned ah0 = *(const unsigned*)(ah + k);
        unsigned ah1 = *(const unsigned*)(ah + rstep + k);
        unsigned ah2 = *(const unsigned*)(ah + k + 8);
        unsigned ah3 = *(const unsigned*)(ah + rstep + k + 8);
        unsigned al0 = *(const unsigned*)(al + k);
        unsigned al1 = *(const unsigned*)(al + rstep + k);
        unsigned al2 = *(const unsigned*)(al + k + 8);
        unsigned al3 = *(const unsigned*)(al + rstep + k + 8);
#pragma unroll
        for (int f = 0; f < NF; f++) {
            unsigned b0 = *(const unsigned*)(bh[f] + k);
            unsigned b1 = *(const unsigned*)(bh[f] + k + 8);
            unsigned c0 = *(const unsigned*)(bl[f] + k);
            unsigned c1 = *(const unsigned*)(bl[f] + k + 8);
            mma16816(acc[f], ah0, ah1, ah2, ah3, b0, b1);  // Ahi*Whi
            mma16816(acc[f], al0, al1, al2, al3, b0, b1);  // Alo*Whi
            mma16816(acc[f], ah0, ah1, ah2, ah3, c0, c1);  // Ahi*Wlo
        }
    }
}

__device__ __forceinline__ void store_split2(bf16* hi, bf16* lo, int idx,
                                             float a, float b)
{
    bf16 ha = __float2bfloat16(a), hb = __float2bfloat16(b);
    bf16 la = __float2bfloat16(a - __bfloat162float(ha));
    bf16 lb = __float2bfloat16(b - __bfloat162float(hb));
    *(bf162*)&hi[idx] = __halves2bfloat162(ha, hb);
    *(bf162*)&lo[idx] = __halves2bfloat162(la, lb);
}

// ------------------- gate tile: 64x32, 8 warps = 4m x 2(n16) ----------------
__device__ __forceinline__ void run_gate_tile(
    const bf16* sWhi, const bf16* sWlo, int ldWt,
    int m0base, int n0base,
    const bf16* A0hi, const bf16* A0lo, int ldA0,
    const bf16* A1hi, const bf16* A1lo, int ldA1, int K1,
    const float* __restrict__ bias,
    float* zout, bf16* rhhi, bf16* rhlo, const float* __restrict__ hf)
{
    const int w = threadIdx.x >> 5;
    const int wm = w & 3, wn = w >> 2;
    const int m0 = m0base + wm * 16;
    const int nloc = wn * 16;
    float acc[2][4] = {};

    const bf16* bWh = sWhi + (size_t)nloc * ldWt;
    const bf16* bWl = sWlo + (size_t)nloc * ldWt;

    mma_sec<256, 2>(A0hi + (size_t)m0 * ldA0, A0lo + (size_t)m0 * ldA0, ldA0,
                    bWh, bWl, ldWt, 0, acc);
    if (K1 == 256)
        mma_sec<256, 2>(A1hi + (size_t)m0 * ldA1, A1lo + (size_t)m0 * ldA1, ldA1,
                        bWh, bWl, ldWt, 256, acc);
    else
        mma_sec<64, 2>(A1hi + (size_t)m0 * ldA1, A1lo + (size_t)m0 * ldA1, ldA1,
                       bWh, bWl, ldWt, 256, acc);

    const int lane = threadIdx.x & 31;
    const int g = lane >> 2, q = lane & 3;
    const bool isZ = (n0base < HID);
#pragma unroll
    for (int f = 0; f < 2; f++) {
        int n = n0base + nloc + f * 8 + q * 2;
        float bx = bias[n], by = bias[n + 1];
#pragma unroll
        for (int h = 0; h < 2; h++) {
            int r = m0 + g + h * 8;
            float v0 = acc[f][h * 2 + 0] + bx;
            float v1 = acc[f][h * 2 + 1] + by;
            float s0 = 1.f / (1.f + __expf(-v0));
            float s1 = 1.f / (1.f + __expf(-v1));
            if (isZ) {
                *(float2*)&zout[r * HID + n] = make_float2(s0, s1);
            } else {
                int c = n - HID;
                float p0 = s0 * hf[r * HID + c];
                float p1 = s1 * hf[r * HID + c + 1];
                store_split2(rhhi, rhlo, r * HID + c, p0, p1);
            }
        }
    }
}

// --------------- candidate tile: 64x16, 8 warps = 4m x 2(n8) ----------------
__device__ __forceinline__ void run_cand_tile(
    const bf16* sWhi, const bf16* sWlo, int ldWt,
    int m0base, int n0base,
    const bf16* A0hi, const bf16* A0lo, int ldA0,
    const bf16* A1hi, const bf16* A1lo, int ldA1, int K1,
    const float* __restrict__ bias,
    const float* __restrict__ zin, const float* __restrict__ hof,
    float* houtf, bf16* houthi, bf16* houtlo)
{
    const int w = threadIdx.x >> 5;
    const int wm = w & 3, wn = w >> 2;
    const int m0 = m0base + wm * 16;
    const int nloc = wn * 8;
    float acc[1][4] = {};

    const bf16* bWh = sWhi + (size_t)nloc * ldWt;
    const bf16* bWl = sWlo + (size_t)nloc * ldWt;

    mma_sec<256, 1>(A0hi + (size_t)m0 * ldA0, A0lo + (size_t)m0 * ldA0, ldA0,
                    bWh, bWl, ldWt, 0, acc);
    if (K1 == 256)
        mma_sec<256, 1>(A1hi + (size_t)m0 * ldA1, A1lo + (size_t)m0 * ldA1, ldA1,
                        bWh, bWl, ldWt, 256, acc);
    else
        mma_sec<64, 1>(A1hi + (size_t)m0 * ldA1, A1lo + (size_t)m0 * ldA1, ldA1,
                       bWh, bWl, ldWt, 256, acc);

    const int lane = threadIdx.x & 31;
    const int g = lane >> 2, q = lane & 3;
    int n = n0base + nloc + q * 2;
    float bx = bias[n], by = bias[n + 1];
#pragma unroll
    for (int h = 0; h < 2; h++) {
        int r = m0 + g + h * 8;
        float v0 = acc[0][h * 2 + 0] + bx;
        float v1 = acc[0][h * 2 + 1] + by;
        float t0 = tanhf(v0);
        float t1 = tanhf(v1);
        float2 z  = *(const float2*)&zin[r * HID + n];
        float2 ho = *(const float2*)&hof[r * HID + n];
        float h0n = (1.f - z.x) * ho.x + z.x * t0;
        float h1n = (1.f - z.y) * ho.y + z.y * t1;
        *(float2*)&houtf[r * HID + n] = make_float2(h0n, h1n);
        store_split2(houthi, houtlo, r * HID + n, h0n, h1n);
    }
}

// ----------------------- one-time weight preload ----------------------------
// Wt[n][k] = W[k][n0+n], split into bf16 hi/lo, row stride ldWt.
__device__ void preload_wt(bf16* shi, bf16* slo,
                           const float* __restrict__ W, int ldW,
                           int n0, int NT, int K, int ldWt)
{
    for (int idx = threadIdx.x; idx < NT * K; idx += NTHR) {
        int n = idx % NT;
        int k = idx / NT;
        float v = W[(size_t)k * ldW + n0 + n];
        bf16 hi = __float2bfloat16(v);
        shi[(size_t)n * ldWt + k] = hi;
        slo[(size_t)n * ldWt + k] = __float2bfloat16(v - __bfloat162float(hi));
    }
}

// ---------------------------- persistent kernel -----------------------------
__global__ void __launch_bounds__(NTHR, 1)
rnn_kernel(const float* __restrict__ x,
           const float* __restrict__ Wz0, const float* __restrict__ bz0,
           const float* __restrict__ Wc0, const float* __restrict__ bc0,
           const float* __restrict__ Wz1, const float* __restrict__ bz1,
           const float* __restrict__ Wc1, const float* __restrict__ bc1,
           const float* __restrict__ gamma, const float* __restrict__ beta,
           float* __restrict__ out)
{
    extern __shared__ bf16 smem[];
    bf16* sAhi = smem;
    bf16* sAlo = smem + SA_ELEMS;
    bf16* sBhi = smem + 2 * SA_ELEMS;
    bf16* sBlo = smem + 2 * SA_ELEMS + SB_ELEMS;
    __shared__ float red[16];

    const int bid = blockIdx.x;
    const bool isG1 = (bid < 64);
    const bool isG0 = (bid >= 64 && bid < 128);
    const int tA = isG1 ? bid : bid - 64;     // gate tile: 4m x 16n
    const int tAM = tA >> 4, tAN = tA & 15;
    const int tB = tA;                        // cand tile: 4m x 16n
    const int tBM = tB >> 4, tBN = tB & 15;

    // ---- init: sanitize + split x, zero states ----
    {
        int gtid = bid * NTHR + threadIdx.x;
        int gs = NCTA * NTHR;
        for (size_t i = gtid; i < (size_t)BATCHN * SEQN * IN_DIM; i += gs) {
            float v = x[i];
            if (v != v) v = 0.f;
            else if (isinf(v)) v = (v > 0.f) ? 10.f : -10.f;
            bf16 hi = __float2bfloat16(v);
            g_xhi[i] = hi;
            g_xlo[i] = __float2bfloat16(v - __bfloat162float(hi));
        }
        bf16 bz = __float2bfloat16(0.f);
        for (int i = gtid; i < BATCHN * HID; i += gs) {
            g_h0f[0][i] = 0.f; g_h0hi[0][i] = bz; g_h0lo[0][i] = bz;
            g_h1f[i] = 0.f;    g_h1hi[i] = bz;    g_h1lo[i] = bz;
        }
    }

    // ---- one-time resident weight preload (per-CTA, own smem only) ----
    if (isG1) {
        preload_wt(sAhi, sAlo, Wz1, 3 * HID, tAN * 32, 32, 2 * HID, 520);
        preload_wt(sBhi, sBlo, Wc1, HID,     tBN * 16, 16, 2 * HID, 520);
    } else if (isG0) {
        preload_wt(sAhi, sAlo, Wz0, 3 * HID, tAN * 32, 32, HID + IN_DIM, 328);
        preload_wt(sBhi, sBlo, Wc0, HID,     tBN * 16, 16, HID + IN_DIM, 328);
    }
    grid_sync();

    // ---- pipelined recurrence ----
    for (int st = 0; st <= SEQN; ++st) {
        const float* h0f  = g_h0f[st & 1];
        const bf16*  h0hi = g_h0hi[st & 1];
        const bf16*  h0lo = g_h0lo[st & 1];
        float* h0fN  = g_h0f[(st + 1) & 1];
        bf16*  h0hiN = g_h0hi[(st + 1) & 1];
        bf16*  h0loN = g_h0lo[(st + 1) & 1];
        const bf16* xthi = g_xhi + (size_t)st * IN_DIM;
        const bf16* xtlo = g_xlo + (size_t)st * IN_DIM;

        // phase A: gates0(st) || gates1(st-1)
        if (isG1) {
            if (st > 0)
                run_gate_tile(sAhi, sAlo, 520, tAM * 64, tAN * 32,
                              g_h1hi, g_h1lo, HID, h0hi, h0lo, HID, 256,
                              bz1, g_z1, g_rh1hi, g_rh1lo, g_h1f);
        } else if (isG0) {
            if (st < SEQN)
                run_gate_tile(sAhi, sAlo, 328, tAM * 64, tAN * 32,
                              h0hi, h0lo, HID, xthi, xtlo, LDXE, 64,
                              bz0, g_z0, g_rh0hi, g_rh0lo, h0f);
        }
        grid_sync();

        // phase B: cand0(st) || cand1(st-1)
        if (isG1) {
            if (st > 0)
                run_cand_tile(sBhi, sBlo, 520, tBM * 64, tBN * 16,
                              g_rh1hi, g_rh1lo, HID, h0hi, h0lo, HID, 256,
                              bc1, g_z1, g_h1f, g_h1f, g_h1hi, g_h1lo);
        } else if (isG0) {
            if (st < SEQN)
                run_cand_tile(sBhi, sBlo, 328, tBM * 64, tBN * 16,
                              g_rh0hi, g_rh0lo, HID, xthi, xtlo, LDXE, 64,
                              bc0, g_z0, h0f, h0fN, h0hiN, h0loN);
        }
        grid_sync();
    }

    // ---- LayerNorm on final h1 ----
    {
        const int tid = threadIdx.x;
        const int wid = tid >> 5, lane = tid & 31;
        for (int b = bid; b < BATCHN; b += NCTA) {
            float v = g_h1f[b * HID + tid];
            float sum = v, sq = v * v;
#pragma unroll
            for (int off = 16; off; off >>= 1) {
                sum += __shfl_xor_sync(0xFFFFFFFFu, sum, off);
                sq  += __shfl_xor_sync(0xFFFFFFFFu, sq,  off);
            }
            if (lane == 0) { red[wid] = sum; red[8 + wid] = sq; }
            __syncthreads();
            float ts = 0.f, tq = 0.f;
#pragma unroll
            for (int w = 0; w < 8; w++) { ts += red[w]; tq += red[8 + w]; }
            float mean = ts * (1.f / HID);
            float var  = tq * (1.f / HID) - mean * mean;
            float rstd = rsqrtf(var + 1e-5f);
            out[b * HID + tid] = (v - mean) * rstd * gamma[tid] + beta[tid];
            __syncthreads();
        }
    }
}

extern "C" void kernel_launch(void* const* d_in, const int* in_sizes, int n_in,
                              void* d_out, int out_size) {
    (void)in_sizes; (void)n_in; (void)out_size;
    const float* x     = (const float*)d_in[0];
    const float* Wz0   = (const float*)d_in[1];
    const float* bz0   = (const float*)d_in[2];
    const float* Wc0   = (const float*)d_in[3];
    const float* bc0   = (const float*)d_in[4];
    const float* Wz1   = (const float*)d_in[5];
    const float* bz1   = (const float*)d_in[6];
    const float* Wc1   = (const float*)d_in[7];
    const float* bc1   = (const float*)d_in[8];
    const float* gamma = (const float*)d_in[9];
    const float* beta  = (const float*)d_in[10];
    float* out = (float*)d_out;

    cudaFuncSetAttribute(rnn_kernel,
                         cudaFuncAttributeMaxDynamicSharedMemorySize, SMEM_BYTES);
    rnn_kernel<<<NCTA, NTHR, SMEM_BYTES>>>(x, Wz0, bz0, Wc0, bc0,
                                           Wz1, bz1, Wc1, bc1, gamma, beta, out);
}

// round 8
// speedup vs baseline: 1.9752x; 1.8072x over previous
#include <cuda_runtime.h>
#include <cuda_bf16.h>
#include <math.h>

#define BATCHN 256
#define SEQN   512
#define IN_DIM 64
#define HID    256
#define NCTA   128
#define NTHR   256
#define LDXE   (SEQN * IN_DIM)

typedef __nv_bfloat16  bf16;
typedef __nv_bfloat162 bf162;

// ---------------- persistent device state (no allocation allowed) -----------
__device__ bf16  g_xhi[(size_t)BATCHN * SEQN * IN_DIM];
__device__ bf16  g_xlo[(size_t)BATCHN * SEQN * IN_DIM];
__device__ float g_h0f[2][BATCHN * HID];
__device__ bf16  g_h0hi[2][BATCHN * HID];
__device__ bf16  g_h0lo[2][BATCHN * HID];
__device__ float g_h1f[BATCHN * HID];
__device__ bf16  g_h1hi[BATCHN * HID];
__device__ bf16  g_h1lo[BATCHN * HID];
__device__ float g_z0[BATCHN * HID];
__device__ float g_z1[BATCHN * HID];
__device__ bf16  g_rh0hi[BATCHN * HID];
__device__ bf16  g_rh0lo[BATCHN * HID];
__device__ bf16  g_rh1hi[BATCHN * HID];
__device__ bf16  g_rh1lo[BATCHN * HID];

__device__ unsigned g_count = 0;
__device__ volatile unsigned g_gen = 0;

// ---------------------------- grid barrier ----------------------------------
__device__ __forceinline__ void grid_sync() {
    __syncthreads();
    if (threadIdx.x == 0) {
        __threadfence();
        unsigned gen = g_gen;
        unsigned a = atomicAdd(&g_count, 1u);
        if (a == NCTA - 1) {
            g_count = 0;
            __threadfence();
            g_gen = gen + 1;
        } else {
            while (g_gen == gen) { }
            __threadfence();
        }
    }
    __syncthreads();
}

// --------------------- shared memory layout (bf16 units) --------------------
#define WST 520             // W row stride (bank-stride 4 mod 32: conflict-free)
#define AST 136             // staged A row stride (bank-stride 4 mod 32)
#define A_TERM (64 * AST)
#define A_BUF  (2 * A_TERM)
#define OFF_WGH 0
#define OFF_WGL (32 * WST)
#define OFF_WCH (2 * 32 * WST)
#define OFF_WCL (OFF_WCH + 16 * WST)
#define OFF_A   (OFF_WCH + 2 * 16 * WST)
#define SMEM_ELEMS (OFF_A + 2 * A_BUF)
#define SMEM_BYTES (SMEM_ELEMS * 2)

__device__ __forceinline__ void cp16(void* dst_smem, const void* src_gmem) {
    unsigned u = (unsigned)__cvta_generic_to_shared(dst_smem);
    asm volatile("cp.async.cg.shared.global [%0], [%1], 16;"
                 :: "r"(u), "l"(src_gmem) : "memory");
}

struct Ck { const bf16* hi; const bf16* lo; int ld; int kw; };

// Stage one [64 x kw] hi+lo chunk into sA[buf].
__device__ __forceinline__ void stage_chunk(bf16* sm, int buf, const Ck c) {
    const int lg   = (c.kw == 128) ? 4 : 3;       // nseg = kw/8
    const int nseg = 1 << lg;
    const int tot  = 64 << lg;
    bf16* dh = sm + OFF_A + buf * A_BUF;
    bf16* dl = dh + A_TERM;
    for (int i = threadIdx.x; i < tot; i += NTHR) {
        int row = i >> lg, sg = i & (nseg - 1);
        int doff = row * AST + sg * 8;
        size_t soff = (size_t)row * c.ld + sg * 8;
        cp16(dh + doff, c.hi + soff);
        cp16(dl + doff, c.lo + soff);
    }
    asm volatile("cp.async.commit_group;" ::: "memory");
}

// ------------------------------- mma helper ---------------------------------
__device__ __forceinline__ void mma16816(float* c,
    unsigned a0, unsigned a1, unsigned a2, unsigned a3,
    unsigned b0, unsigned b1)
{
    asm("mma.sync.aligned.m16n8k16.row.col.f32.bf16.bf16.f32 "
        "{%0,%1,%2,%3}, {%4,%5,%6,%7}, {%8,%9}, {%0,%1,%2,%3};"
        : "+f"(c[0]), "+f"(c[1]), "+f"(c[2]), "+f"(c[3])
        : "r"(a0), "r"(a1), "r"(a2), "r"(a3), "r"(b0), "r"(b1));
}

// 3-term split MMA over one staged chunk (A from smem, W resident in smem).
template<int KW, int NF>
__device__ __forceinline__ void mma_chunk(
    const bf16* sm, int buf, int wBase, int loDelta,
    int nloc, int kbase, int m0loc, float (&acc)[NF][4])
{
    const int lane = threadIdx.x & 31;
    const int g = lane >> 2, q = lane & 3;
    const bf16* aH = sm + OFF_A + buf * A_BUF + (m0loc + g) * AST + q * 2;
    const bf16* aL = aH + A_TERM;
    const bf16* bH[NF];
#pragma unroll
    for (int f = 0; f < NF; f++)
        bH[f] = sm + wBase + (size_t)(nloc + f * 8 + g) * WST + kbase + q * 2;

#pragma unroll
    for (int k = 0; k < KW; k += 16) {
        unsigned ah0 = *(const unsigned*)(aH + k);
        unsigned ah1 = *(const unsigned*)(aH + 8 * AST + k);
        unsigned ah2 = *(const unsigned*)(aH + k + 8);
        unsigned ah3 = *(const unsigned*)(aH + 8 * AST + k + 8);
        unsigned al0 = *(const unsigned*)(aL + k);
        unsigned al1 = *(const unsigned*)(aL + 8 * AST + k);
        unsigned al2 = *(const unsigned*)(aL + k + 8);
        unsigned al3 = *(const unsigned*)(aL + 8 * AST + k + 8);
#pragma unroll
        for (int f = 0; f < NF; f++) {
            unsigned b0 = *(const unsigned*)(bH[f] + k);
            unsigned b1 = *(const unsigned*)(bH[f] + k + 8);
            unsigned c0 = *(const unsigned*)(bH[f] + loDelta + k);
            unsigned c1 = *(const unsigned*)(bH[f] + loDelta + k + 8);
            mma16816(acc[f], ah0, ah1, ah2, ah3, b0, b1);  // Ahi*Whi
            mma16816(acc[f], al0, al1, al2, al3, b0, b1);  // Alo*Whi
            mma16816(acc[f], ah0, ah1, ah2, ah3, c0, c1);  // Ahi*Wlo
        }
    }
}

__device__ __forceinline__ void store_split2(bf16* hi, bf16* lo, int idx,
                                             float a, float b)
{
    bf16 ha = __float2bfloat16(a), hb = __float2bfloat16(b);
    bf16 la = __float2bfloat16(a - __bfloat162float(ha));
    bf16 lb = __float2bfloat16(b - __bfloat162float(hb));
    *(bf162*)&hi[idx] = __halves2bfloat162(ha, hb);
    *(bf162*)&lo[idx] = __halves2bfloat162(la, lb);
}

// ------------------- gate tile: 64x32, warps 4m x 2n ------------------------
__device__ __forceinline__ void run_gate(
    bf16* sm, int ctaM0, int n0base, const Ck* cks, int nc,
    const float* __restrict__ bias,
    float* zout, bf16* rhhi, bf16* rhlo, const float* __restrict__ hf)
{
    const int w = threadIdx.x >> 5;
    const int wm = w & 3, wn = w >> 2;
    float acc[2][4] = {};
    int kb = 0;
    for (int c = 0; c < nc; c++) {
        if (c == 0) stage_chunk(sm, 0, cks[0]);
        if (c + 1 < nc) {
            stage_chunk(sm, (c + 1) & 1, cks[c + 1]);
            asm volatile("cp.async.wait_group 1;" ::: "memory");
        } else {
            asm volatile("cp.async.wait_group 0;" ::: "memory");
        }
        __syncthreads();
        if (cks[c].kw == 128)
            mma_chunk<128, 2>(sm, c & 1, OFF_WGH, OFF_WGL - OFF_WGH,
                              wn * 16, kb, wm * 16, acc);
        else
            mma_chunk<64, 2>(sm, c & 1, OFF_WGH, OFF_WGL - OFF_WGH,
                             wn * 16, kb, wm * 16, acc);
        kb += cks[c].kw;
        __syncthreads();
    }

    const int lane = threadIdx.x & 31;
    const int g = lane >> 2, q = lane & 3;
    const bool isZ = (n0base < HID);
#pragma unroll
    for (int f = 0; f < 2; f++) {
        int n = n0base + wn * 16 + f * 8 + q * 2;
        float bx = bias[n], by = bias[n + 1];
#pragma unroll
        for (int h = 0; h < 2; h++) {
            int r = ctaM0 + wm * 16 + g + h * 8;
            float v0 = acc[f][h * 2 + 0] + bx;
            float v1 = acc[f][h * 2 + 1] + by;
            float s0 = 1.f / (1.f + __expf(-v0));
            float s1 = 1.f / (1.f + __expf(-v1));
            if (isZ) {
                *(float2*)&zout[r * HID + n] = make_float2(s0, s1);
            } else {
                int c = n - HID;
                float p0 = s0 * hf[r * HID + c];
                float p1 = s1 * hf[r * HID + c + 1];
                store_split2(rhhi, rhlo, r * HID + c, p0, p1);
            }
        }
    }
}

// --------------- candidate tile: 64x16, warps 4m x 2n -----------------------
__device__ __forceinline__ void run_cand(
    bf16* sm, int ctaM0, int n0base, const Ck* cks, int nc,
    const float* __restrict__ bias,
    const float* __restrict__ zin, const float* __restrict__ hof,
    float* houtf, bf16* houthi, bf16* houtlo)
{
    const int w = threadIdx.x >> 5;
    const int wm = w & 3, wn = w >> 2;
    float acc[1][4] = {};
    int kb = 0;
    for (int c = 0; c < nc; c++) {
        if (c == 0) stage_chunk(sm, 0, cks[0]);
        if (c + 1 < nc) {
            stage_chunk(sm, (c + 1) & 1, cks[c + 1]);
            asm volatile("cp.async.wait_group 1;" ::: "memory");
        } else {
            asm volatile("cp.async.wait_group 0;" ::: "memory");
        }
        __syncthreads();
        if (cks[c].kw == 128)
            mma_chunk<128, 1>(sm, c & 1, OFF_WCH, OFF_WCL - OFF_WCH,
                              wn * 8, kb, wm * 16, acc);
        else
            mma_chunk<64, 1>(sm, c & 1, OFF_WCH, OFF_WCL - OFF_WCH,
                             wn * 8, kb, wm * 16, acc);
        kb += cks[c].kw;
        __syncthreads();
    }

    const int lane = threadIdx.x & 31;
    const int g = lane >> 2, q = lane & 3;
    int n = n0base + wn * 8 + q * 2;
    float bx = bias[n], by = bias[n + 1];
#pragma unroll
    for (int h = 0; h < 2; h++) {
        int r = ctaM0 + wm * 16 + g + h * 8;
        float v0 = acc[0][h * 2 + 0] + bx;
        float v1 = acc[0][h * 2 + 1] + by;
        float t0 = tanhf(v0);
        float t1 = tanhf(v1);
        float2 z  = *(const float2*)&zin[r * HID + n];
        float2 ho = *(const float2*)&hof[r * HID + n];
        float h0n = (1.f - z.x) * ho.x + z.x * t0;
        float h1n = (1.f - z.y) * ho.y + z.y * t1;
        *(float2*)&houtf[r * HID + n] = make_float2(h0n, h1n);
        store_split2(houthi, houtlo, r * HID + n, h0n, h1n);
    }
}

// ----------------------- one-time weight preload ----------------------------
__device__ __forceinline__ void preload_wt(bf16* shi, bf16* slo,
                                           const float* __restrict__ W, int ldW,
                                           int n0, int NT, int K)
{
    for (int idx = threadIdx.x; idx < NT * K; idx += NTHR) {
        int n = idx % NT;
        int k = idx / NT;
        float v = W[(size_t)k * ldW + n0 + n];
        bf16 hi = __float2bfloat16(v);
        shi[(size_t)n * WST + k] = hi;
        slo[(size_t)n * WST + k] = __float2bfloat16(v - __bfloat162float(hi));
    }
}

// ---------------------------- persistent kernel -----------------------------
__global__ void __launch_bounds__(NTHR, 1)
rnn_kernel(const float* __restrict__ x,
           const float* __restrict__ Wz0, const float* __restrict__ bz0,
           const float* __restrict__ Wc0, const float* __restrict__ bc0,
           const float* __restrict__ Wz1, const float* __restrict__ bz1,
           const float* __restrict__ Wc1, const float* __restrict__ bc1,
           const float* __restrict__ gamma, const float* __restrict__ beta,
           float* __restrict__ out)
{
    extern __shared__ bf16 sm[];
    __shared__ float red[16];

    const int bid = blockIdx.x;
    const bool isG1 = (bid < 64);
    const int tA = bid & 63;
    const int tAM = tA >> 4, tAN = tA & 15;
    const int m0 = tAM * 64;

    // ---- init: sanitize + split x, zero states ----
    {
        int gtid = bid * NTHR + threadIdx.x;
        int gs = NCTA * NTHR;
        for (size_t i = gtid; i < (size_t)BATCHN * SEQN * IN_DIM; i += gs) {
            float v = x[i];
            if (v != v) v = 0.f;
            else if (isinf(v)) v = (v > 0.f) ? 10.f : -10.f;
            bf16 hi = __float2bfloat16(v);
            g_xhi[i] = hi;
            g_xlo[i] = __float2bfloat16(v - __bfloat162float(hi));
        }
        bf16 bz = __float2bfloat16(0.f);
        for (int i = gtid; i < BATCHN * HID; i += gs) {
            g_h0f[0][i] = 0.f; g_h0hi[0][i] = bz; g_h0lo[0][i] = bz;
            g_h1f[i] = 0.f;    g_h1hi[i] = bz;    g_h1lo[i] = bz;
        }
    }

    // ---- resident weight preload ----
    if (isG1) {
        preload_wt(sm + OFF_WGH, sm + OFF_WGL, Wz1, 3 * HID, tAN * 32, 32, 2 * HID);
        preload_wt(sm + OFF_WCH, sm + OFF_WCL, Wc1, HID,     tAN * 16, 16, 2 * HID);
    } else {
        preload_wt(sm + OFF_WGH, sm + OFF_WGL, Wz0, 3 * HID, tAN * 32, 32, HID + IN_DIM);
        preload_wt(sm + OFF_WCH, sm + OFF_WCL, Wc0, HID,     tAN * 16, 16, HID + IN_DIM);
    }
    grid_sync();

    // ---- pipelined recurrence ----
    for (int st = 0; st <= SEQN; ++st) {
        const float* h0f  = g_h0f[st & 1];
        const bf16*  h0hi = g_h0hi[st & 1];
        const bf16*  h0lo = g_h0lo[st & 1];
        float* h0fN  = g_h0f[(st + 1) & 1];
        bf16*  h0hiN = g_h0hi[(st + 1) & 1];
        bf16*  h0loN = g_h0lo[(st + 1) & 1];
        const bf16* xthi = g_xhi + (size_t)st * IN_DIM;
        const bf16* xtlo = g_xlo + (size_t)st * IN_DIM;

        // phase A: gates0(st) on G0 || gates1(st-1) on G1
        if (isG1) {
            if (st > 0) {
                Ck cks[4] = {
                    {g_h1hi + m0 * HID,       g_h1lo + m0 * HID,       HID, 128},
                    {g_h1hi + m0 * HID + 128, g_h1lo + m0 * HID + 128, HID, 128},
                    {h0hi  + m0 * HID,        h0lo  + m0 * HID,        HID, 128},
                    {h0hi  + m0 * HID + 128,  h0lo  + m0 * HID + 128,  HID, 128}};
                run_gate(sm, m0, tAN * 32, cks, 4, bz1,
                         g_z1, g_rh1hi, g_rh1lo, g_h1f);
            }
        } else {
            if (st < SEQN) {
                Ck cks[3] = {
                    {h0hi + m0 * HID,        h0lo + m0 * HID,        HID, 128},
                    {h0hi + m0 * HID + 128,  h0lo + m0 * HID + 128,  HID, 128},
                    {xthi + (size_t)m0 * LDXE, xtlo + (size_t)m0 * LDXE, LDXE, 64}};
                run_gate(sm, m0, tAN * 32, cks, 3, bz0,
                         g_z0, g_rh0hi, g_rh0lo, h0f);
            }
        }
        grid_sync();

        // phase B: cand0(st) on G0 || cand1(st-1) on G1
        if (isG1) {
            if (st > 0) {
                Ck cks[4] = {
                    {g_rh1hi + m0 * HID,       g_rh1lo + m0 * HID,       HID, 128},
                    {g_rh1hi + m0 * HID + 128, g_rh1lo + m0 * HID + 128, HID, 128},
                    {h0hi   + m0 * HID,        h0lo   + m0 * HID,        HID, 128},
                    {h0hi   + m0 * HID + 128,  h0lo   + m0 * HID + 128,  HID, 128}};
                run_cand(sm, m0, tAN * 16, cks, 4, bc1,
                         g_z1, g_h1f, g_h1f, g_h1hi, g_h1lo);
            }
        } else {
            if (st < SEQN) {
                Ck cks[3] = {
                    {g_rh0hi + m0 * HID,       g_rh0lo + m0 * HID,       HID, 128},
                    {g_rh0hi + m0 * HID + 128, g_rh0lo + m0 * HID + 128, HID, 128},
                    {xthi + (size_t)m0 * LDXE, xtlo + (size_t)m0 * LDXE, LDXE, 64}};
                run_cand(sm, m0, tAN * 16, cks, 3, bc0,
                         g_z0, h0f, h0fN, h0hiN, h0loN);
            }
        }
        grid_sync();
    }

    // ---- LayerNorm on final h1 ----
    {
        const int tid = threadIdx.x;
        const int wid = tid >> 5, lane = tid & 31;
        for (int b = bid; b < BATCHN; b += NCTA) {
            float v = g_h1f[b * HID + tid];
            float sum = v, sq = v * v;
#pragma unroll
            for (int off = 16; off; off >>= 1) {
                sum += __shfl_xor_sync(0xFFFFFFFFu, sum, off);
                sq  += __shfl_xor_sync(0xFFFFFFFFu, sq,  off);
            }
            if (lane == 0) { red[wid] = sum; red[8 + wid] = sq; }
            __syncthreads();
            float ts = 0.f, tq = 0.f;
#pragma unroll
            for (int w = 0; w < 8; w++) { ts += red[w]; tq += red[8 + w]; }
            float mean = ts * (1.f / HID);
            float var  = tq * (1.f / HID) - mean * mean;
            float rstd = rsqrtf(var + 1e-5f);
            out[b * HID + tid] = (v - mean) * rstd * gamma[tid] + beta[tid];
            __syncthreads();
        }
    }
}

extern "C" void kernel_launch(void* const* d_in, const int* in_sizes, int n_in,
                              void* d_out, int out_size) {
    (void)in_sizes; (void)n_in; (void)out_size;
    const float* x     = (const float*)d_in[0];
    const float* Wz0   = (const float*)d_in[1];
    const float* bz0   = (const float*)d_in[2];
    const float* Wc0   = (const float*)d_in[3];
    const float* bc0   = (const float*)d_in[4];
    const float* Wz1   = (const float*)d_in[5];
    const float* bz1   = (const float*)d_in[6];
    const float* Wc1   = (const float*)d_in[7];
    const float* bc1   = (const float*)d_in[8];
    const float* gamma = (const float*)d_in[9];
    const float* beta  = (const float*)d_in[10];
    float* out = (float*)d_out;

    cudaFuncSetAttribute(rnn_kernel,
                         cudaFuncAttributeMaxDynamicSharedMemorySize, SMEM_BYTES);
    rnn_kernel<<<NCTA, NTHR, SMEM_BYTES>>>(x, Wz0, bz0, Wc0, bc0,
                                           Wz1, bz1, Wc1, bc1, gamma, beta, out);
}